// round 1
// baseline (speedup 1.0000x reference)
#include <cuda_runtime.h>
#include <math.h>

#define NN 100000
#define NG 256

// ---------------- scratch (device globals; no allocations allowed) ----------
__device__ float g_hA[(size_t)NN * 200];
__device__ float g_hB[(size_t)NN * 200];
__device__ float g_agg[(size_t)NN * 200];
__device__ float g_invdeg[NN];
__device__ float g_pool[NG * 1000];
__device__ float g_m1[NG * 500];
__device__ float g_m2[NG * 250];
__device__ int   g_gstart[NG + 1];

// ---------------- degree ----------------------------------------------------
__global__ void deg_kernel(const int* __restrict__ dst, float* __restrict__ deg, int E) {
    int e = blockIdx.x * blockDim.x + threadIdx.x;
    if (e < E) atomicAdd(&deg[dst[e]], 1.0f);
}

__global__ void invdeg_kernel(float* __restrict__ deg, int n) {
    int i = blockIdx.x * blockDim.x + threadIdx.x;
    if (i < n) deg[i] = 1.0f / fmaxf(deg[i], 1.0f);
}

// ---------------- graph segment offsets (batch is sorted) -------------------
__global__ void gstart_kernel(const int* __restrict__ batch, int* __restrict__ gstart, int n) {
    __shared__ int cnt[NG];
    for (int i = threadIdx.x; i < NG; i += blockDim.x) cnt[i] = 0;
    __syncthreads();
    for (int i = threadIdx.x; i < n; i += blockDim.x) atomicAdd(&cnt[batch[i]], 1);
    __syncthreads();
    if (threadIdx.x == 0) {
        int s = 0;
        for (int g = 0; g < NG; g++) { gstart[g] = s; s += cnt[g]; }
        gstart[NG] = s;
    }
}

// ---------------- edge scatter (mean-agg numerator) -------------------------
// 200-dim: 50 float4 lanes per edge, 5 edges per 256-thread block.
__global__ void __launch_bounds__(256) scatter200_kernel(
    const int* __restrict__ src, const int* __restrict__ dst,
    const float* __restrict__ h, float* __restrict__ agg, int E)
{
    int t = threadIdx.x;
    if (t >= 250) return;
    int sub = t / 50, lane = t % 50;
    long e = (long)blockIdx.x * 5 + sub;
    if (e >= E) return;
    int s = src[e], d = dst[e];
    float4 v = ((const float4*)(h + (size_t)s * 200))[lane];
    atomicAdd(((float4*)(agg + (size_t)d * 200)) + lane, v);  // sm_90+: RED.v4
}

// 11-dim first layer: 11 scalar lanes per edge, 23 edges per block.
__global__ void __launch_bounds__(256) scatter11_kernel(
    const int* __restrict__ src, const int* __restrict__ dst,
    const float* __restrict__ x, float* __restrict__ agg, int E)
{
    int t = threadIdx.x;
    if (t >= 253) return;
    int sub = t / 11, lane = t % 11;
    long e = (long)blockIdx.x * 23 + sub;
    if (e >= E) return;
    int s = src[e], d = dst[e];
    atomicAdd(&agg[(size_t)d * 11 + lane], x[(size_t)s * 11 + lane]);
}

// ---------------- fused dual-source GEMM ------------------------------------
// C[m,n] = act( sum_k A0[m,k]*s0[m]*W0[n,k] + (A1? sum_k A1[m,k]*W1[n,k] : 0) + bias[n] )
// Tile 128x64x16, 256 threads, 8x4 register tile.
__global__ void __launch_bounds__(256) gemm_kernel(
    const float* __restrict__ A0, const float* __restrict__ s0,
    const float* __restrict__ W0,
    const float* __restrict__ A1, const float* __restrict__ W1,
    const float* __restrict__ bias, float* __restrict__ C,
    int M, int N, int K, int relu)
{
    const int BM = 128, BN = 64, BK = 16;
    __shared__ float As[BK][BM];
    __shared__ float Bs[BK][BN];
    int tid = threadIdx.x;
    int tx = tid & 15, ty = tid >> 4;
    int m0 = blockIdx.x * BM, n0 = blockIdx.y * BN;

    float acc[8][4];
#pragma unroll
    for (int r = 0; r < 8; r++)
#pragma unroll
        for (int c = 0; c < 4; c++) acc[r][c] = 0.0f;

    int nsrc = A1 ? 2 : 1;
    for (int sIdx = 0; sIdx < nsrc; sIdx++) {
        const float* A  = sIdx ? A1 : A0;
        const float* W  = sIdx ? W1 : W0;
        const float* sc = sIdx ? (const float*)0 : s0;
        for (int k0 = 0; k0 < K; k0 += BK) {
#pragma unroll
            for (int i = tid; i < BM * BK; i += 256) {
                int row = i >> 4, kk = i & 15;
                int m = m0 + row, k = k0 + kk;
                float v = 0.0f;
                if (m < M && k < K) {
                    v = A[(size_t)m * K + k];
                    if (sc) v *= sc[m];
                }
                As[kk][row] = v;
            }
#pragma unroll
            for (int i = tid; i < BN * BK; i += 256) {
                int row = i >> 4, kk = i & 15;
                int n = n0 + row, k = k0 + kk;
                Bs[kk][row] = (n < N && k < K) ? W[(size_t)n * K + k] : 0.0f;
            }
            __syncthreads();
#pragma unroll
            for (int kk = 0; kk < BK; kk++) {
                float a[8], b[4];
#pragma unroll
                for (int r = 0; r < 8; r++) a[r] = As[kk][ty * 8 + r];
#pragma unroll
                for (int c = 0; c < 4; c++) b[c] = Bs[kk][tx * 4 + c];
#pragma unroll
                for (int r = 0; r < 8; r++)
#pragma unroll
                    for (int c = 0; c < 4; c++) acc[r][c] += a[r] * b[c];
            }
            __syncthreads();
        }
    }

#pragma unroll
    for (int r = 0; r < 8; r++) {
        int m = m0 + ty * 8 + r;
        if (m >= M) continue;
#pragma unroll
        for (int c = 0; c < 4; c++) {
            int n = n0 + tx * 4 + c;
            if (n >= N) continue;
            float v = acc[r][c] + bias[n];
            if (relu) v = fmaxf(v, 0.0f);
            C[(size_t)m * N + n] = v;
        }
    }
}

// ---------------- per-layer graph mean-pool into pool[:, off:off+200] -------
__global__ void pool_kernel(const float* __restrict__ h, const int* __restrict__ gstart,
                            float* __restrict__ pool, int off)
{
    int g = blockIdx.x;
    int f = threadIdx.x;
    if (f >= 200) return;
    int s = gstart[g], e = gstart[g + 1];
    float acc = 0.0f;
    for (int n = s; n < e; n++) acc += h[(size_t)n * 200 + f];
    float c = (float)(e - s);
    pool[(size_t)g * 1000 + off + f] = acc / fmaxf(c, 1.0f);
}

// ---------------- final 250 -> 1 + sigmoid ----------------------------------
__global__ void mlp3_kernel(const float* __restrict__ in, const float* __restrict__ w,
                            const float* __restrict__ b, float* __restrict__ out)
{
    int g = threadIdx.x;  // 256 graphs
    float acc = b[0];
    for (int k = 0; k < 250; k++) acc += in[g * 250 + k] * w[k];
    out[g] = 1.0f / (1.0f + expf(-acc));
}

// ---------------- launch ----------------------------------------------------
extern "C" void kernel_launch(void* const* d_in, const int* in_sizes, int n_in,
                              void* d_out, int out_size)
{
    const float* x     = (const float*)d_in[0];
    const int*   ei    = (const int*)d_in[1];
    const int*   batch = (const int*)d_in[2];
    const float* Wl[5], *bl[5], *Wr[5];
    for (int i = 0; i < 5; i++) {
        Wl[i] = (const float*)d_in[3 + 3 * i];
        bl[i] = (const float*)d_in[4 + 3 * i];
        Wr[i] = (const float*)d_in[5 + 3 * i];
    }
    const float* pw1 = (const float*)d_in[18];
    const float* pb1 = (const float*)d_in[19];
    const float* pw2 = (const float*)d_in[20];
    const float* pb2 = (const float*)d_in[21];
    const float* pw3 = (const float*)d_in[22];
    const float* pb3 = (const float*)d_in[23];
    float* out = (float*)d_out;

    int E = in_sizes[1] / 2;
    const int* src = ei;
    const int* dst = ei + E;

    float *hA, *hB, *agg, *invdeg, *pool, *m1, *m2;
    int* gstart;
    cudaGetSymbolAddress((void**)&hA, g_hA);
    cudaGetSymbolAddress((void**)&hB, g_hB);
    cudaGetSymbolAddress((void**)&agg, g_agg);
    cudaGetSymbolAddress((void**)&invdeg, g_invdeg);
    cudaGetSymbolAddress((void**)&pool, g_pool);
    cudaGetSymbolAddress((void**)&m1, g_m1);
    cudaGetSymbolAddress((void**)&m2, g_m2);
    cudaGetSymbolAddress((void**)&gstart, g_gstart);

    cudaMemsetAsync(invdeg, 0, NN * sizeof(float));
    cudaMemsetAsync(pool, 0, NG * 1000 * sizeof(float));

    deg_kernel<<<(E + 255) / 256, 256>>>(dst, invdeg, E);
    invdeg_kernel<<<(NN + 255) / 256, 256>>>(invdeg, NN);
    gstart_kernel<<<1, 512>>>(batch, gstart, NN);

    const float* hin = x;
    int Kin = 11;
    float* hout = hA;

    for (int L = 0; L < 5; L++) {
        cudaMemsetAsync(agg, 0, (size_t)NN * Kin * sizeof(float));
        if (L == 0) {
            scatter11_kernel<<<(E + 22) / 23, 256>>>(src, dst, hin, agg, E);
        } else {
            scatter200_kernel<<<(E + 4) / 5, 256>>>(src, dst, hin, agg, E);
        }
        dim3 grid((NN + 127) / 128, (200 + 63) / 64);
        gemm_kernel<<<grid, 256>>>(agg, invdeg, Wl[L], hin, Wr[L], bl[L], hout,
                                   NN, 200, Kin, 1);
        pool_kernel<<<NG, 256>>>(hout, gstart, pool, L * 200);
        hin = hout;
        Kin = 200;
        hout = (hout == hA) ? hB : hA;
    }

    // projection head: 1000 -> 500 -> 250 -> 1 (no activations, then sigmoid)
    {
        dim3 g1((NG + 127) / 128, (500 + 63) / 64);
        gemm_kernel<<<g1, 256>>>(pool, (const float*)0, pw1,
                                 (const float*)0, (const float*)0, pb1, m1,
                                 NG, 500, 1000, 0);
        dim3 g2((NG + 127) / 128, (250 + 63) / 64);
        gemm_kernel<<<g2, 256>>>(m1, (const float*)0, pw2,
                                 (const float*)0, (const float*)0, pb2, m2,
                                 NG, 250, 500, 0);
        mlp3_kernel<<<1, 256>>>(m2, pw3, pb3, out);
    }
}

// round 2
// speedup vs baseline: 2.2649x; 2.2649x over previous
#include <cuda_runtime.h>
#include <math.h>

#define NN 100000
#define NG 256
#define MAXE 3400000

// ---------------- scratch (device globals; no allocations allowed) ----------
__device__ float g_hA[(size_t)NN * 200];
__device__ float g_hB[(size_t)NN * 200];
__device__ float g_agg[(size_t)NN * 200];
__device__ float g_invdeg[NN];
__device__ float g_pool[NG * 1000];
__device__ float g_m1[NG * 500];
__device__ float g_m2[NG * 250];
__device__ int   g_gstart[NG + 1];
__device__ int   g_rowcnt[NN];
__device__ int   g_rowptr[NN + 1];
__device__ int   g_cursor[NN];
__device__ int   g_col[MAXE];

// ---------------- CSR build -------------------------------------------------
__global__ void count_kernel(const int* __restrict__ dst, int* __restrict__ cnt, int E) {
    int e = blockIdx.x * blockDim.x + threadIdx.x;
    if (e < E) atomicAdd(&cnt[dst[e]], 1);
}

// single-block exclusive scan over counts; also invdeg + cursor init
__global__ void __launch_bounds__(1024) scan_kernel(
    const int* __restrict__ cnt, int* __restrict__ rowptr,
    int* __restrict__ cursor, float* __restrict__ invdeg, int n)
{
    __shared__ int sh[1024];
    __shared__ int carry;
    int tid = threadIdx.x;
    if (tid == 0) { carry = 0; rowptr[0] = 0; }
    __syncthreads();
    for (int base = 0; base < n; base += 1024) {
        int i = base + tid;
        int v = (i < n) ? cnt[i] : 0;
        sh[tid] = v;
        __syncthreads();
        // inclusive Hillis-Steele scan
        for (int off = 1; off < 1024; off <<= 1) {
            int t = (tid >= off) ? sh[tid - off] : 0;
            __syncthreads();
            sh[tid] += t;
            __syncthreads();
        }
        int incl = sh[tid];
        int c = carry;
        if (i < n) {
            int excl = c + incl - v;
            rowptr[i + 1] = c + incl;
            cursor[i] = excl;
            invdeg[i] = 1.0f / (float)max(v, 1);
        }
        __syncthreads();
        if (tid == 1023) carry = c + sh[1023];
        __syncthreads();
    }
}

__global__ void fill_kernel(const int* __restrict__ src, const int* __restrict__ dst,
                            int* __restrict__ cursor, int* __restrict__ col, int E) {
    int e = blockIdx.x * blockDim.x + threadIdx.x;
    if (e < E) {
        int d = dst[e];
        int pos = atomicAdd(&cursor[d], 1);
        col[pos] = src[e];
    }
}

// ---------------- graph segment offsets (batch is sorted) -------------------
__global__ void gstart_kernel(const int* __restrict__ batch, int* __restrict__ gstart, int n) {
    __shared__ int cnt[NG];
    for (int i = threadIdx.x; i < NG; i += blockDim.x) cnt[i] = 0;
    __syncthreads();
    for (int i = threadIdx.x; i < n; i += blockDim.x) atomicAdd(&cnt[batch[i]], 1);
    __syncthreads();
    if (threadIdx.x == 0) {
        int s = 0;
        for (int g = 0; g < NG; g++) { gstart[g] = s; s += cnt[g]; }
        gstart[NG] = s;
    }
}

// ---------------- CSR gather (mean aggregation, invdeg fused) ---------------
__global__ void __launch_bounds__(256) gather200_kernel(
    const int* __restrict__ rowptr, const int* __restrict__ col,
    const float* __restrict__ h, const float* __restrict__ invdeg,
    float* __restrict__ agg, int nNodes)
{
    int t = threadIdx.x;
    if (t >= 250) return;
    int n = blockIdx.x * 5 + t / 50;
    if (n >= nNodes) return;
    int lane = t % 50;
    int s = rowptr[n], e = rowptr[n + 1];
    float4 acc = make_float4(0.f, 0.f, 0.f, 0.f);
    const float4* h4 = (const float4*)h;
    for (int j = s; j < e; j++) {
        int sc = __ldg(&col[j]);
        float4 v = h4[(size_t)sc * 50 + lane];
        acc.x += v.x; acc.y += v.y; acc.z += v.z; acc.w += v.w;
    }
    float id = invdeg[n];
    acc.x *= id; acc.y *= id; acc.z *= id; acc.w *= id;
    ((float4*)agg)[(size_t)n * 50 + lane] = acc;
}

__global__ void __launch_bounds__(256) gather11_kernel(
    const int* __restrict__ rowptr, const int* __restrict__ col,
    const float* __restrict__ x, const float* __restrict__ invdeg,
    float* __restrict__ agg, int nNodes)
{
    int t = threadIdx.x;
    if (t >= 253) return;
    int n = blockIdx.x * 23 + t / 11;
    if (n >= nNodes) return;
    int lane = t % 11;
    int s = rowptr[n], e = rowptr[n + 1];
    float acc = 0.f;
    for (int j = s; j < e; j++) {
        int sc = __ldg(&col[j]);
        acc += x[(size_t)sc * 11 + lane];
    }
    agg[(size_t)n * 11 + lane] = acc * invdeg[n];
}

// ---------------- tf32 tensor-core GEMM (dual source, fused bias+relu) ------
// C[m,n] = act( A0[m,:] @ W0[n,:] + (A1 ? A1[m,:] @ W1[n,:] : 0) + bias[n] )
// Block 128x64x32, 256 threads = 8 warps (4 along M x 2 along N), warp 32x32.
__device__ __forceinline__ unsigned f2tf(float f) {
    unsigned u;
    asm("cvt.rna.tf32.f32 %0, %1;" : "=r"(u) : "f"(f));
    return u;
}

#define GBM 128
#define GBN 64
#define GBK 32

__global__ void __launch_bounds__(256) gemm_tf32_kernel(
    const float* __restrict__ A0, const float* __restrict__ W0,
    const float* __restrict__ A1, const float* __restrict__ W1,
    const float* __restrict__ bias, float* __restrict__ C,
    int M, int N, int K, int relu)
{
    __shared__ unsigned As[GBM][GBK + 4];
    __shared__ unsigned Bs[GBN][GBK + 4];

    int tid = threadIdx.x;
    int wid = tid >> 5;
    int lane = tid & 31;
    int wm = wid & 3;   // warp row (0..3) -> 32 rows each
    int wn = wid >> 2;  // warp col (0..1) -> 32 cols each
    int lr = lane >> 2; // 0..7
    int lc = lane & 3;  // 0..3
    int m0 = blockIdx.x * GBM, n0 = blockIdx.y * GBN;

    float acc[2][4][4];
#pragma unroll
    for (int mt = 0; mt < 2; mt++)
#pragma unroll
        for (int nt = 0; nt < 4; nt++)
#pragma unroll
            for (int c = 0; c < 4; c++) acc[mt][nt][c] = 0.f;

    int nsrc = A1 ? 2 : 1;
    for (int sIdx = 0; sIdx < nsrc; sIdx++) {
        const float* A = sIdx ? A1 : A0;
        const float* W = sIdx ? W1 : W0;
        int vec = ((K & 3) == 0);

        for (int k0 = 0; k0 < K; k0 += GBK) {
            if (vec) {
#pragma unroll
                for (int i = 0; i < 4; i++) {
                    int lin = tid + i * 256;      // 0..1023
                    int kq = lin & 7, row = lin >> 3;
                    int m = m0 + row, k = k0 + kq * 4;
                    float4 v = make_float4(0.f, 0.f, 0.f, 0.f);
                    if (m < M && k < K) v = *(const float4*)(A + (size_t)m * K + k);
                    As[row][kq * 4 + 0] = f2tf(v.x);
                    As[row][kq * 4 + 1] = f2tf(v.y);
                    As[row][kq * 4 + 2] = f2tf(v.z);
                    As[row][kq * 4 + 3] = f2tf(v.w);
                }
#pragma unroll
                for (int i = 0; i < 2; i++) {
                    int lin = tid + i * 256;      // 0..511
                    int kq = lin & 7, nr = lin >> 3;
                    int n = n0 + nr, k = k0 + kq * 4;
                    float4 v = make_float4(0.f, 0.f, 0.f, 0.f);
                    if (n < N && k < K) v = *(const float4*)(W + (size_t)n * K + k);
                    Bs[nr][kq * 4 + 0] = f2tf(v.x);
                    Bs[nr][kq * 4 + 1] = f2tf(v.y);
                    Bs[nr][kq * 4 + 2] = f2tf(v.z);
                    Bs[nr][kq * 4 + 3] = f2tf(v.w);
                }
            } else {
#pragma unroll
                for (int i = 0; i < 16; i++) {
                    int lin = tid + i * 256;      // 0..4095
                    int kk = lin & 31, row = lin >> 5;
                    int m = m0 + row, k = k0 + kk;
                    float v = (m < M && k < K) ? A[(size_t)m * K + k] : 0.f;
                    As[row][kk] = f2tf(v);
                }
#pragma unroll
                for (int i = 0; i < 8; i++) {
                    int lin = tid + i * 256;      // 0..2047
                    int kk = lin & 31, nr = lin >> 5;
                    int n = n0 + nr, k = k0 + kk;
                    float v = (n < N && k < K) ? W[(size_t)n * K + k] : 0.f;
                    Bs[nr][kk] = f2tf(v);
                }
            }
            __syncthreads();

#pragma unroll
            for (int ks = 0; ks < 4; ks++) {
                unsigned a[2][4], b[4][2];
#pragma unroll
                for (int mt = 0; mt < 2; mt++) {
                    int r = wm * 32 + mt * 16 + lr;
                    a[mt][0] = As[r][ks * 8 + lc];
                    a[mt][1] = As[r + 8][ks * 8 + lc];
                    a[mt][2] = As[r][ks * 8 + lc + 4];
                    a[mt][3] = As[r + 8][ks * 8 + lc + 4];
                }
#pragma unroll
                for (int nt = 0; nt < 4; nt++) {
                    int n = wn * 32 + nt * 8 + lr;
                    b[nt][0] = Bs[n][ks * 8 + lc];
                    b[nt][1] = Bs[n][ks * 8 + lc + 4];
                }
#pragma unroll
                for (int mt = 0; mt < 2; mt++)
#pragma unroll
                    for (int nt = 0; nt < 4; nt++) {
                        asm volatile(
                            "mma.sync.aligned.m16n8k8.row.col.f32.tf32.tf32.f32 "
                            "{%0,%1,%2,%3}, {%4,%5,%6,%7}, {%8,%9}, {%0,%1,%2,%3};"
                            : "+f"(acc[mt][nt][0]), "+f"(acc[mt][nt][1]),
                              "+f"(acc[mt][nt][2]), "+f"(acc[mt][nt][3])
                            : "r"(a[mt][0]), "r"(a[mt][1]), "r"(a[mt][2]), "r"(a[mt][3]),
                              "r"(b[nt][0]), "r"(b[nt][1]));
                    }
            }
            __syncthreads();
        }
    }

    // epilogue: c0 -> (r, c), c1 -> (r, c+1), c2 -> (r+8, c), c3 -> (r+8, c+1)
#pragma unroll
    for (int mt = 0; mt < 2; mt++) {
#pragma unroll
        for (int nt = 0; nt < 4; nt++) {
            int r = m0 + wm * 32 + mt * 16 + lr;
            int c = n0 + wn * 32 + nt * 8 + lc * 2;
#pragma unroll
            for (int q = 0; q < 4; q++) {
                int rr = r + (q >> 1) * 8;
                int cc = c + (q & 1);
                if (rr < M && cc < N) {
                    float v = acc[mt][nt][q] + bias[cc];
                    if (relu) v = fmaxf(v, 0.f);
                    C[(size_t)rr * N + cc] = v;
                }
            }
        }
    }
}

// ---------------- per-layer graph mean-pool into pool[:, off:off+200] -------
__global__ void pool_kernel(const float* __restrict__ h, const int* __restrict__ gstart,
                            float* __restrict__ pool, int off)
{
    int g = blockIdx.x;
    int f = threadIdx.x;
    if (f >= 200) return;
    int s = gstart[g], e = gstart[g + 1];
    float acc = 0.0f;
    for (int n = s; n < e; n++) acc += h[(size_t)n * 200 + f];
    float c = (float)(e - s);
    pool[(size_t)g * 1000 + off + f] = acc / fmaxf(c, 1.0f);
}

// ---------------- final 250 -> 1 + sigmoid ----------------------------------
__global__ void mlp3_kernel(const float* __restrict__ in, const float* __restrict__ w,
                            const float* __restrict__ b, float* __restrict__ out)
{
    int g = threadIdx.x;  // 256 graphs
    float acc = b[0];
    for (int k = 0; k < 250; k++) acc += in[g * 250 + k] * w[k];
    out[g] = 1.0f / (1.0f + expf(-acc));
}

// ---------------- launch ----------------------------------------------------
extern "C" void kernel_launch(void* const* d_in, const int* in_sizes, int n_in,
                              void* d_out, int out_size)
{
    const float* x     = (const float*)d_in[0];
    const int*   ei    = (const int*)d_in[1];
    const int*   batch = (const int*)d_in[2];
    const float* Wl[5], *bl[5], *Wr[5];
    for (int i = 0; i < 5; i++) {
        Wl[i] = (const float*)d_in[3 + 3 * i];
        bl[i] = (const float*)d_in[4 + 3 * i];
        Wr[i] = (const float*)d_in[5 + 3 * i];
    }
    const float* pw1 = (const float*)d_in[18];
    const float* pb1 = (const float*)d_in[19];
    const float* pw2 = (const float*)d_in[20];
    const float* pb2 = (const float*)d_in[21];
    const float* pw3 = (const float*)d_in[22];
    const float* pb3 = (const float*)d_in[23];
    float* out = (float*)d_out;

    int E = in_sizes[1] / 2;
    const int* src = ei;
    const int* dst = ei + E;

    float *hA, *hB, *agg, *invdeg, *pool, *m1, *m2;
    int *gstart, *rowcnt, *rowptr, *cursor, *col;
    cudaGetSymbolAddress((void**)&hA, g_hA);
    cudaGetSymbolAddress((void**)&hB, g_hB);
    cudaGetSymbolAddress((void**)&agg, g_agg);
    cudaGetSymbolAddress((void**)&invdeg, g_invdeg);
    cudaGetSymbolAddress((void**)&pool, g_pool);
    cudaGetSymbolAddress((void**)&m1, g_m1);
    cudaGetSymbolAddress((void**)&m2, g_m2);
    cudaGetSymbolAddress((void**)&gstart, g_gstart);
    cudaGetSymbolAddress((void**)&rowcnt, g_rowcnt);
    cudaGetSymbolAddress((void**)&rowptr, g_rowptr);
    cudaGetSymbolAddress((void**)&cursor, g_cursor);
    cudaGetSymbolAddress((void**)&col, g_col);

    // CSR build (by dst) + invdeg
    cudaMemsetAsync(rowcnt, 0, NN * sizeof(int));
    count_kernel<<<(E + 255) / 256, 256>>>(dst, rowcnt, E);
    scan_kernel<<<1, 1024>>>(rowcnt, rowptr, cursor, invdeg, NN);
    fill_kernel<<<(E + 255) / 256, 256>>>(src, dst, cursor, col, E);
    gstart_kernel<<<1, 512>>>(batch, gstart, NN);

    const float* hin = x;
    int Kin = 11;
    float* hout = hA;

    for (int L = 0; L < 5; L++) {
        if (L == 0) {
            gather11_kernel<<<(NN + 22) / 23, 256>>>(rowptr, col, hin, invdeg, agg, NN);
        } else {
            gather200_kernel<<<(NN + 4) / 5, 256>>>(rowptr, col, hin, invdeg, agg, NN);
        }
        dim3 grid((NN + GBM - 1) / GBM, (200 + GBN - 1) / GBN);
        gemm_tf32_kernel<<<grid, 256>>>(agg, Wl[L], hin, Wr[L], bl[L], hout,
                                        NN, 200, Kin, 1);
        pool_kernel<<<NG, 256>>>(hout, gstart, pool, L * 200);
        hin = hout;
        Kin = 200;
        hout = (hout == hA) ? hB : hA;
    }

    // projection head: 1000 -> 500 -> 250 -> 1 (no activations, then sigmoid)
    {
        dim3 g1((NG + GBM - 1) / GBM, (500 + GBN - 1) / GBN);
        gemm_tf32_kernel<<<g1, 256>>>(pool, pw1, (const float*)0, (const float*)0,
                                      pb1, m1, NG, 500, 1000, 0);
        dim3 g2((NG + GBM - 1) / GBM, (250 + GBN - 1) / GBN);
        gemm_tf32_kernel<<<g2, 256>>>(m1, pw2, (const float*)0, (const float*)0,
                                      pb2, m2, NG, 250, 500, 0);
        mlp3_kernel<<<1, 256>>>(m2, pw3, pb3, out);
    }
}

// round 3
// speedup vs baseline: 5.4880x; 2.4230x over previous
#include <cuda_runtime.h>
#include <cuda_fp16.h>
#include <math.h>

#define NN 100000
#define NG 256
#define MAXE 3400000
#define NB_SCAN ((NN + 1023) / 1024)

// ---------------- scratch (device globals; no allocations allowed) ----------
__device__ __half g_hA[(size_t)NN * 200];
__device__ __half g_hB[(size_t)NN * 200];
__device__ __half g_agg[(size_t)NN * 200];   // layer1 aliases this as float (needs 4.4MB < 40MB)
__device__ float g_invdeg[NN];
__device__ float g_pool[NG * 1000];
__device__ float g_m1[NG * 500];
__device__ float g_m2[NG * 250];
__device__ int   g_gstart[NG + 1];
__device__ int   g_gcnt[NG];
__device__ float g_ginv[NG];
__device__ int   g_rowcnt[NN];
__device__ int   g_rowptr[NN + 1];
__device__ int   g_cursor[NN];
__device__ int   g_col[MAXE];
__device__ int   g_bsum[NB_SCAN];
__device__ int   g_boff[NB_SCAN];

// ---------------- CSR build -------------------------------------------------
__global__ void count_kernel(const int* __restrict__ dst, int* __restrict__ cnt, int E) {
    int e = blockIdx.x * blockDim.x + threadIdx.x;
    if (e < E) atomicAdd(&cnt[dst[e]], 1);
}

// pass 1: per-block inclusive scan, store to rowptr[i+1] (local), block totals
__global__ void __launch_bounds__(1024) blockscan_kernel(
    const int* __restrict__ cnt, int* __restrict__ rowptr, int* __restrict__ bsum, int n)
{
    __shared__ int sh[1024];
    int tid = threadIdx.x;
    int i = blockIdx.x * 1024 + tid;
    int v = (i < n) ? cnt[i] : 0;
    sh[tid] = v;
    __syncthreads();
    for (int off = 1; off < 1024; off <<= 1) {
        int t = (tid >= off) ? sh[tid - off] : 0;
        __syncthreads();
        sh[tid] += t;
        __syncthreads();
    }
    if (i < n) rowptr[i + 1] = sh[tid];
    if (tid == 1023) bsum[blockIdx.x] = sh[1023];
}

// pass 2: exclusive scan of block totals (tiny)
__global__ void bsumscan_kernel(const int* __restrict__ bsum, int* __restrict__ boff, int nb) {
    if (threadIdx.x == 0) {
        int s = 0;
        for (int b = 0; b < nb; b++) { boff[b] = s; s += bsum[b]; }
    }
}

// pass 3: apply offsets; emit cursor + invdeg
__global__ void apply_kernel(const int* __restrict__ cnt, int* __restrict__ rowptr,
                             const int* __restrict__ boff, int* __restrict__ cursor,
                             float* __restrict__ invdeg, int n)
{
    int i = blockIdx.x * blockDim.x + threadIdx.x;
    if (i >= n) return;
    int total = rowptr[i + 1] + boff[i >> 10];
    rowptr[i + 1] = total;
    int c = cnt[i];
    cursor[i] = total - c;
    invdeg[i] = 1.0f / (float)max(c, 1);
    if (i == 0) rowptr[0] = 0;
}

__global__ void fill_kernel(const int* __restrict__ src, const int* __restrict__ dst,
                            int* __restrict__ cursor, int* __restrict__ col, int E) {
    int e = blockIdx.x * blockDim.x + threadIdx.x;
    if (e < E) {
        int d = dst[e];
        int pos = atomicAdd(&cursor[d], 1);
        col[pos] = src[e];
    }
}

// ---------------- graph segment offsets (batch is sorted) -------------------
__global__ void gcount_kernel(const int* __restrict__ batch, int* __restrict__ gcnt, int n) {
    int i = blockIdx.x * blockDim.x + threadIdx.x;
    if (i < n) atomicAdd(&gcnt[batch[i]], 1);
}

__global__ void gscan_kernel(const int* __restrict__ gcnt, int* __restrict__ gstart,
                             float* __restrict__ ginv)
{
    if (threadIdx.x == 0) {
        int s = 0;
        for (int g = 0; g < NG; g++) {
            gstart[g] = s;
            s += gcnt[g];
        }
        gstart[NG] = s;
    }
    __syncthreads();
    int g = threadIdx.x;
    if (g < NG) ginv[g] = 1.0f / (float)max(gcnt[g], 1);
}

// ---------------- CSR gather (mean aggregation, invdeg fused), fp16 ---------
__global__ void __launch_bounds__(256) gather200h_kernel(
    const int* __restrict__ rowptr, const int* __restrict__ col,
    const __half* __restrict__ h, const float* __restrict__ invdeg,
    __half* __restrict__ agg, int nNodes)
{
    int t = threadIdx.x;
    if (t >= 250) return;
    int n = blockIdx.x * 10 + t / 25;
    if (n >= nNodes) return;
    int lane = t % 25;                  // 25 x uint4 (8 halves) = 200 halves
    int s = rowptr[n], e = rowptr[n + 1];
    float acc[8];
#pragma unroll
    for (int q = 0; q < 8; q++) acc[q] = 0.f;
    for (int j = s; j < e; j++) {
        int sc = __ldg(&col[j]);
        uint4 v = *(const uint4*)(h + (size_t)sc * 200 + lane * 8);
        const __half2* hp = (const __half2*)&v;
#pragma unroll
        for (int q = 0; q < 4; q++) {
            float2 f = __half22float2(hp[q]);
            acc[2 * q]     += f.x;
            acc[2 * q + 1] += f.y;
        }
    }
    float id = invdeg[n];
    __half2 o[4];
#pragma unroll
    for (int q = 0; q < 4; q++)
        o[q] = __floats2half2_rn(acc[2 * q] * id, acc[2 * q + 1] * id);
    *(uint4*)(agg + (size_t)n * 200 + lane * 8) = *(uint4*)o;
}

__global__ void __launch_bounds__(256) gather11_kernel(
    const int* __restrict__ rowptr, const int* __restrict__ col,
    const float* __restrict__ x, const float* __restrict__ invdeg,
    float* __restrict__ agg, int nNodes)
{
    int t = threadIdx.x;
    if (t >= 253) return;
    int n = blockIdx.x * 23 + t / 11;
    if (n >= nNodes) return;
    int lane = t % 11;
    int s = rowptr[n], e = rowptr[n + 1];
    float acc = 0.f;
    for (int j = s; j < e; j++) {
        int sc = __ldg(&col[j]);
        acc += x[(size_t)sc * 11 + lane];
    }
    agg[(size_t)n * 11 + lane] = acc * invdeg[n];
}

// ---------------- fp16 tensor-core GEMM (dual source, fused bias+relu) ------
// C[m,n] = relu( A0[m,:]@W0[n,:] + A1[m,:]@W1[n,:] + bias[n] ), fp16 out.
// A0/A1 fp16 [M][K], W fp32 [N][K]. Requires K % 8 == 0.
// Block 128x64x32, 8 warps (4M x 2N), warp tile 32x32, mma m16n8k16.
__global__ void __launch_bounds__(256) gemm_f16_kernel(
    const __half* __restrict__ A0, const __half* __restrict__ A1,
    const float* __restrict__ W0, const float* __restrict__ W1,
    const float* __restrict__ bias, __half* __restrict__ C,
    int M, int N, int K)
{
    __shared__ __half As[128][40];
    __shared__ __half Bs[64][40];

    int tid = threadIdx.x;
    int wid = tid >> 5, lane = tid & 31;
    int wm = wid & 3, wn = wid >> 2;
    int lr = lane >> 2, lc = lane & 3;
    int m0 = blockIdx.x * 128, n0 = blockIdx.y * 64;

    float acc[2][4][4];
#pragma unroll
    for (int mt = 0; mt < 2; mt++)
#pragma unroll
        for (int nt = 0; nt < 4; nt++)
#pragma unroll
            for (int q = 0; q < 4; q++) acc[mt][nt][q] = 0.f;

    for (int sIdx = 0; sIdx < 2; sIdx++) {
        const __half* A = sIdx ? A1 : A0;
        const float*  W = sIdx ? W1 : W0;

        for (int k0 = 0; k0 < K; k0 += 32) {
            // stage A: 128 rows x 32 halves, uint4 = 8 halves
#pragma unroll
            for (int i = 0; i < 2; i++) {
                int lin = tid + i * 256;       // 0..511
                int kq = lin & 3, row = lin >> 2;
                int m = m0 + row, k = k0 + kq * 8;
                uint4 v = make_uint4(0, 0, 0, 0);
                if (m < M && k + 8 <= K) v = *(const uint4*)(A + (size_t)m * K + k);
                *(uint4*)&As[row][kq * 8] = v;
            }
            // stage B: W fp32 -> fp16; 64 rows x 32 floats, float4 each
#pragma unroll
            for (int i = 0; i < 2; i++) {
                int lin = tid + i * 256;       // 0..511
                int kq = lin & 7, row = lin >> 3;
                int n = n0 + row, k = k0 + kq * 4;
                float4 v = make_float4(0.f, 0.f, 0.f, 0.f);
                if (n < N && k + 4 <= K) v = *(const float4*)(W + (size_t)n * K + k);
                *(__half2*)&Bs[row][kq * 4]     = __floats2half2_rn(v.x, v.y);
                *(__half2*)&Bs[row][kq * 4 + 2] = __floats2half2_rn(v.z, v.w);
            }
            __syncthreads();

#pragma unroll
            for (int ks = 0; ks < 2; ks++) {
                int ko = ks * 16;
                unsigned a[2][4], b[4][2];
#pragma unroll
                for (int mt = 0; mt < 2; mt++) {
                    int r = wm * 32 + mt * 16 + lr;
                    a[mt][0] = *(const unsigned*)&As[r][ko + lc * 2];
                    a[mt][1] = *(const unsigned*)&As[r + 8][ko + lc * 2];
                    a[mt][2] = *(const unsigned*)&As[r][ko + lc * 2 + 8];
                    a[mt][3] = *(const unsigned*)&As[r + 8][ko + lc * 2 + 8];
                }
#pragma unroll
                for (int nt = 0; nt < 4; nt++) {
                    int n = wn * 32 + nt * 8 + lr;
                    b[nt][0] = *(const unsigned*)&Bs[n][ko + lc * 2];
                    b[nt][1] = *(const unsigned*)&Bs[n][ko + lc * 2 + 8];
                }
#pragma unroll
                for (int mt = 0; mt < 2; mt++)
#pragma unroll
                    for (int nt = 0; nt < 4; nt++) {
                        asm volatile(
                            "mma.sync.aligned.m16n8k16.row.col.f32.f16.f16.f32 "
                            "{%0,%1,%2,%3}, {%4,%5,%6,%7}, {%8,%9}, {%0,%1,%2,%3};"
                            : "+f"(acc[mt][nt][0]), "+f"(acc[mt][nt][1]),
                              "+f"(acc[mt][nt][2]), "+f"(acc[mt][nt][3])
                            : "r"(a[mt][0]), "r"(a[mt][1]), "r"(a[mt][2]), "r"(a[mt][3]),
                              "r"(b[nt][0]), "r"(b[nt][1]));
                    }
            }
            __syncthreads();
        }
    }

#pragma unroll
    for (int mt = 0; mt < 2; mt++) {
#pragma unroll
        for (int nt = 0; nt < 4; nt++) {
            int r = m0 + wm * 32 + mt * 16 + lr;
            int c = n0 + wn * 32 + nt * 8 + lc * 2;
#pragma unroll
            for (int q = 0; q < 4; q++) {
                int rr = r + (q >> 1) * 8;
                int cc = c + (q & 1);
                if (rr < M && cc < N) {
                    float v = fmaxf(acc[mt][nt][q] + bias[cc], 0.f);
                    C[(size_t)rr * N + cc] = __float2half(v);
                }
            }
        }
    }
}

// ---------------- tf32 GEMM (layer 1 + projection head) ---------------------
__device__ __forceinline__ unsigned f2tf(float f) {
    unsigned u;
    asm("cvt.rna.tf32.f32 %0, %1;" : "=r"(u) : "f"(f));
    return u;
}

__global__ void __launch_bounds__(256) gemm_tf32_kernel(
    const float* __restrict__ A0, const float* __restrict__ W0,
    const float* __restrict__ A1, const float* __restrict__ W1,
    const float* __restrict__ bias, void* __restrict__ Cv,
    int M, int N, int K, int relu, int out_half)
{
    __shared__ unsigned As[128][36];
    __shared__ unsigned Bs[64][36];

    int tid = threadIdx.x;
    int wid = tid >> 5, lane = tid & 31;
    int wm = wid & 3, wn = wid >> 2;
    int lr = lane >> 2, lc = lane & 3;
    int m0 = blockIdx.x * 128, n0 = blockIdx.y * 64;

    float acc[2][4][4];
#pragma unroll
    for (int mt = 0; mt < 2; mt++)
#pragma unroll
        for (int nt = 0; nt < 4; nt++)
#pragma unroll
            for (int q = 0; q < 4; q++) acc[mt][nt][q] = 0.f;

    int nsrc = A1 ? 2 : 1;
    for (int sIdx = 0; sIdx < nsrc; sIdx++) {
        const float* A = sIdx ? A1 : A0;
        const float* W = sIdx ? W1 : W0;

        for (int k0 = 0; k0 < K; k0 += 32) {
#pragma unroll
            for (int i = 0; i < 16; i++) {
                int lin = tid + i * 256;
                int kk = lin & 31, row = lin >> 5;
                int m = m0 + row, k = k0 + kk;
                float v = (m < M && k < K) ? A[(size_t)m * K + k] : 0.f;
                As[row][kk] = f2tf(v);
            }
#pragma unroll
            for (int i = 0; i < 8; i++) {
                int lin = tid + i * 256;
                int kk = lin & 31, row = lin >> 5;
                int n = n0 + row, k = k0 + kk;
                float v = (n < N && k < K) ? W[(size_t)n * K + k] : 0.f;
                Bs[row][kk] = f2tf(v);
            }
            __syncthreads();

#pragma unroll
            for (int ks = 0; ks < 4; ks++) {
                unsigned a[2][4], b[4][2];
#pragma unroll
                for (int mt = 0; mt < 2; mt++) {
                    int r = wm * 32 + mt * 16 + lr;
                    a[mt][0] = As[r][ks * 8 + lc];
                    a[mt][1] = As[r + 8][ks * 8 + lc];
                    a[mt][2] = As[r][ks * 8 + lc + 4];
                    a[mt][3] = As[r + 8][ks * 8 + lc + 4];
                }
#pragma unroll
                for (int nt = 0; nt < 4; nt++) {
                    int n = wn * 32 + nt * 8 + lr;
                    b[nt][0] = Bs[n][ks * 8 + lc];
                    b[nt][1] = Bs[n][ks * 8 + lc + 4];
                }
#pragma unroll
                for (int mt = 0; mt < 2; mt++)
#pragma unroll
                    for (int nt = 0; nt < 4; nt++) {
                        asm volatile(
                            "mma.sync.aligned.m16n8k8.row.col.f32.tf32.tf32.f32 "
                            "{%0,%1,%2,%3}, {%4,%5,%6,%7}, {%8,%9}, {%0,%1,%2,%3};"
                            : "+f"(acc[mt][nt][0]), "+f"(acc[mt][nt][1]),
                              "+f"(acc[mt][nt][2]), "+f"(acc[mt][nt][3])
                            : "r"(a[mt][0]), "r"(a[mt][1]), "r"(a[mt][2]), "r"(a[mt][3]),
                              "r"(b[nt][0]), "r"(b[nt][1]));
                    }
            }
            __syncthreads();
        }
    }

#pragma unroll
    for (int mt = 0; mt < 2; mt++) {
#pragma unroll
        for (int nt = 0; nt < 4; nt++) {
            int r = m0 + wm * 32 + mt * 16 + lr;
            int c = n0 + wn * 32 + nt * 8 + lc * 2;
#pragma unroll
            for (int q = 0; q < 4; q++) {
                int rr = r + (q >> 1) * 8;
                int cc = c + (q & 1);
                if (rr < M && cc < N) {
                    float v = acc[mt][nt][q] + bias[cc];
                    if (relu) v = fmaxf(v, 0.f);
                    if (out_half) ((__half*)Cv)[(size_t)rr * N + cc] = __float2half(v);
                    else          ((float*)Cv)[(size_t)rr * N + cc] = v;
                }
            }
        }
    }
}

// ---------------- per-layer graph mean-pool (split 8-ways, atomic) ----------
__global__ void pool_kernel(const __half* __restrict__ h, const int* __restrict__ gstart,
                            const float* __restrict__ ginv, float* __restrict__ pool, int off)
{
    int g = blockIdx.x;
    int chunk = blockIdx.y;
    int f = threadIdx.x;
    if (f >= 200) return;
    int s0 = gstart[g], e0 = gstart[g + 1];
    int len = e0 - s0;
    if (len <= 0) return;
    int per = (len + 7) / 8;
    int s = s0 + chunk * per;
    int e = min(s + per, e0);
    if (s >= e) return;
    float acc = 0.f;
    for (int n = s; n < e; n++) acc += __half2float(h[(size_t)n * 200 + f]);
    atomicAdd(&pool[(size_t)g * 1000 + off + f], acc * ginv[g]);
}

// ---------------- final 250 -> 1 + sigmoid ----------------------------------
__global__ void mlp3_kernel(const float* __restrict__ in, const float* __restrict__ w,
                            const float* __restrict__ b, float* __restrict__ out)
{
    int g = threadIdx.x;
    float acc = b[0];
    for (int k = 0; k < 250; k++) acc += in[g * 250 + k] * w[k];
    out[g] = 1.0f / (1.0f + expf(-acc));
}

// ---------------- launch ----------------------------------------------------
extern "C" void kernel_launch(void* const* d_in, const int* in_sizes, int n_in,
                              void* d_out, int out_size)
{
    const float* x     = (const float*)d_in[0];
    const int*   ei    = (const int*)d_in[1];
    const int*   batch = (const int*)d_in[2];
    const float* Wl[5], *bl[5], *Wr[5];
    for (int i = 0; i < 5; i++) {
        Wl[i] = (const float*)d_in[3 + 3 * i];
        bl[i] = (const float*)d_in[4 + 3 * i];
        Wr[i] = (const float*)d_in[5 + 3 * i];
    }
    const float* pw1 = (const float*)d_in[18];
    const float* pb1 = (const float*)d_in[19];
    const float* pw2 = (const float*)d_in[20];
    const float* pb2 = (const float*)d_in[21];
    const float* pw3 = (const float*)d_in[22];
    const float* pb3 = (const float*)d_in[23];
    float* out = (float*)d_out;

    int E = in_sizes[1] / 2;
    const int* src = ei;
    const int* dst = ei + E;

    __half *hA, *hB, *agg;
    float *invdeg, *pool, *m1, *m2, *ginv;
    int *gstart, *gcnt, *rowcnt, *rowptr, *cursor, *col, *bsum, *boff;
    cudaGetSymbolAddress((void**)&hA, g_hA);
    cudaGetSymbolAddress((void**)&hB, g_hB);
    cudaGetSymbolAddress((void**)&agg, g_agg);
    cudaGetSymbolAddress((void**)&invdeg, g_invdeg);
    cudaGetSymbolAddress((void**)&pool, g_pool);
    cudaGetSymbolAddress((void**)&m1, g_m1);
    cudaGetSymbolAddress((void**)&m2, g_m2);
    cudaGetSymbolAddress((void**)&gstart, g_gstart);
    cudaGetSymbolAddress((void**)&gcnt, g_gcnt);
    cudaGetSymbolAddress((void**)&ginv, g_ginv);
    cudaGetSymbolAddress((void**)&rowcnt, g_rowcnt);
    cudaGetSymbolAddress((void**)&rowptr, g_rowptr);
    cudaGetSymbolAddress((void**)&cursor, g_cursor);
    cudaGetSymbolAddress((void**)&col, g_col);
    cudaGetSymbolAddress((void**)&bsum, g_bsum);
    cudaGetSymbolAddress((void**)&boff, g_boff);

    cudaMemsetAsync(rowcnt, 0, NN * sizeof(int));
    cudaMemsetAsync(gcnt, 0, NG * sizeof(int));
    cudaMemsetAsync(pool, 0, NG * 1000 * sizeof(float));

    // CSR build (by dst) + invdeg
    count_kernel<<<(E + 255) / 256, 256>>>(dst, rowcnt, E);
    blockscan_kernel<<<NB_SCAN, 1024>>>(rowcnt, rowptr, bsum, NN);
    bsumscan_kernel<<<1, 32>>>(bsum, boff, NB_SCAN);
    apply_kernel<<<(NN + 255) / 256, 256>>>(rowcnt, rowptr, boff, cursor, invdeg, NN);
    fill_kernel<<<(E + 255) / 256, 256>>>(src, dst, cursor, col, E);

    // graph segments
    gcount_kernel<<<(NN + 255) / 256, 256>>>(batch, gcnt, NN);
    gscan_kernel<<<1, 256>>>(gcnt, gstart, ginv);

    dim3 pgrid(NG, 8);

    // ---- layer 1 (fp32 inputs, tf32 GEMM, fp16 output) ----
    float* aggf = (float*)agg;
    gather11_kernel<<<(NN + 22) / 23, 256>>>(rowptr, col, x, invdeg, aggf, NN);
    {
        dim3 grid((NN + 127) / 128, (200 + 63) / 64);
        gemm_tf32_kernel<<<grid, 256>>>(aggf, Wl[0], x, Wr[0], bl[0], hA,
                                        NN, 200, 11, 1, 1);
    }
    pool_kernel<<<pgrid, 256>>>(hA, gstart, ginv, pool, 0);

    // ---- layers 2-5 (fp16 everywhere) ----
    const __half* hin = hA;
    __half* hout = hB;
    for (int L = 1; L < 5; L++) {
        gather200h_kernel<<<(NN + 9) / 10, 256>>>(rowptr, col, hin, invdeg, agg, NN);
        dim3 grid((NN + 127) / 128, (200 + 63) / 64);
        gemm_f16_kernel<<<grid, 256>>>(agg, hin, Wl[L], Wr[L], bl[L], hout,
                                       NN, 200, 200);
        pool_kernel<<<pgrid, 256>>>(hout, gstart, ginv, pool, L * 200);
        const __half* t = hin;
        hin = hout;
        hout = (__half*)t;
    }

    // ---- projection head (fp32/tf32) ----
    {
        dim3 g1((NG + 127) / 128, (500 + 63) / 64);
        gemm_tf32_kernel<<<g1, 256>>>(pool, pw1, (const float*)0, (const float*)0,
                                      pb1, m1, NG, 500, 1000, 0, 0);
        dim3 g2((NG + 127) / 128, (250 + 63) / 64);
        gemm_tf32_kernel<<<g2, 256>>>(m1, pw2, (const float*)0, (const float*)0,
                                      pb2, m2, NG, 250, 500, 0, 0);
        mlp3_kernel<<<1, 256>>>(m2, pw3, pb3, out);
    }
}